// round 1
// baseline (speedup 1.0000x reference)
#include <cuda_runtime.h>
#include <cstdint>

// SPP: out = concat([x, maxpool5(x), maxpool9(x), maxpool13(x)], axis=1)
// x: (16, 512, 64, 64) fp32 -> out: (16, 2048, 64, 64) fp32
//
// maxpool9 = maxpool5(maxpool5(x)); maxpool13 = maxpool5(maxpool9)  (exact with -inf pad)
// Each 5x5 pool is separable: row-max5 then col-max5.
// One CTA per (n,c) plane; plane lives in smem the whole time -> HBM traffic
// is exactly 1x read + 4x write (640 MiB total).

#define PITCH 65  // 64 + 1 padding to break smem bank conflicts

__device__ __forceinline__ float fmax5(float a, float b, float c, float d, float e) {
    return fmaxf(fmaxf(fmaxf(a, b), fmaxf(c, d)), e);
}

__global__ __launch_bounds__(256) void spp_kernel(const float* __restrict__ x,
                                                  float* __restrict__ out) {
    __shared__ float A[64 * PITCH];
    __shared__ float B[64 * PITCH];

    const float NEG_INF = __int_as_float(0xff800000);

    const int p   = blockIdx.x;       // plane index: n*512 + c
    const int tid = threadIdx.x;
    const int n   = p >> 9;
    const int c   = p & 511;

    const float* gx   = x + (size_t)p * 4096;
    float*       gout = out + ((size_t)n * 2048 + (size_t)c) * 4096;

    // ---- Load plane into smem (vectorized) and copy straight to out chunk 0 ----
    {
        const float4* gx4 = (const float4*)gx;
        float4*       go4 = (float4*)gout;
#pragma unroll
        for (int i = 0; i < 4; i++) {
            int idx = tid + i * 256;          // float4 index 0..1023
            float4 v = gx4[idx];
            go4[idx] = v;
            int row  = idx >> 4;              // 16 float4 per row
            int col4 = (idx & 15) << 2;
            float* dst = &A[row * PITCH + col4];
            dst[0] = v.x; dst[1] = v.y; dst[2] = v.z; dst[3] = v.w;
        }
    }
    __syncthreads();

    // h-pass mapping: thread -> (row, 16-col segment)
    const int hrow = tid >> 2;
    const int hseg = (tid & 3) << 4;
    // v-pass mapping: thread -> (column, 16-row segment)
    const int vcol  = tid & 63;
    const int vrow0 = (tid >> 6) << 4;

#pragma unroll
    for (int level = 0; level < 3; level++) {
        // ---- horizontal max5: A -> B ----
        {
            float v[20];
            const float* src = &A[hrow * PITCH];
#pragma unroll
            for (int i = 0; i < 20; i++) {
                int col = hseg + i - 2;
                v[i] = (col >= 0 && col < 64) ? src[col] : NEG_INF;
            }
            float* dst = &B[hrow * PITCH + hseg];
#pragma unroll
            for (int j = 0; j < 16; j++)
                dst[j] = fmax5(v[j], v[j + 1], v[j + 2], v[j + 3], v[j + 4]);
        }
        __syncthreads();

        // ---- vertical max5: B -> A (+ write final result to global) ----
        {
            float v[20];
#pragma unroll
            for (int i = 0; i < 20; i++) {
                int row = vrow0 + i - 2;
                v[i] = (row >= 0 && row < 64) ? B[row * PITCH + vcol] : NEG_INF;
            }
            float* gl = gout + (size_t)(level + 1) * 512 * 4096;
#pragma unroll
            for (int j = 0; j < 16; j++) {
                float m = fmax5(v[j], v[j + 1], v[j + 2], v[j + 3], v[j + 4]);
                A[(vrow0 + j) * PITCH + vcol] = m;
                gl[(vrow0 + j) * 64 + vcol]   = m;
            }
        }
        __syncthreads();
    }
}

extern "C" void kernel_launch(void* const* d_in, const int* in_sizes, int n_in,
                              void* d_out, int out_size) {
    const float* x = (const float*)d_in[0];
    float* out = (float*)d_out;
    // 16 * 512 = 8192 planes
    spp_kernel<<<8192, 256>>>(x, out);
}

// round 3
// speedup vs baseline: 1.8002x; 1.8002x over previous
#include <cuda_runtime.h>
#include <cstdint>

// SPP: out = concat([x, maxpool5(x), maxpool9(x), maxpool13(x)], axis=1)
// x: (16, 512, 64, 64) fp32 -> out: (16, 2048, 64, 64) fp32
//
// maxpool9 = maxpool5(maxpool5(x)); maxpool13 = maxpool5(maxpool9)  (exact with -inf pad)
// Each 5x5 pool separable: row-max5 then col-max5. One CTA per (n,c) plane.
//
// R2: fully 128-bit smem/global paths, conflict-free phase mappings:
//   PITCH=68 words -> rows 16B-aligned; pad cols 64..67 = -inf, 4-float guard
//   before row 0 so the h-pass runs 6 unconditional LDS.128 (no predication).
//   h-pass: row = tid&63 (phase bank-quads = r mod 8, conflict-free).
//   v-pass: 4col x 4row tile per thread; 8 LDS.128 + 4 STS.128 + 4 STG.128
//   (lanes 0..15 of an instr write one contiguous 256B row -> coalesced).

#define P 68  // smem row pitch in floats

__device__ __forceinline__ float fmax5(float a, float b, float c, float d, float e) {
    return fmaxf(fmaxf(fmaxf(a, b), fmaxf(c, d)), e);
}

__device__ __forceinline__ float4 vmax5(float4 a, float4 b, float4 c, float4 d, float4 e) {
    float4 r;
    r.x = fmax5(a.x, b.x, c.x, d.x, e.x);
    r.y = fmax5(a.y, b.y, c.y, d.y, e.y);
    r.z = fmax5(a.z, b.z, c.z, d.z, e.z);
    r.w = fmax5(a.w, b.w, c.w, d.w, e.w);
    return r;
}

__global__ __launch_bounds__(256) void spp_kernel(const float* __restrict__ x,
                                                  float* __restrict__ out) {
    __shared__ __align__(16) float Araw[4 + 64 * P];
    __shared__ __align__(16) float B[64 * P];
    float* A = Araw + 4;  // A[-4..-1] is the guard read by row 0's left halo load

    const float NI = __int_as_float(0xff800000);
    const float4 NI4 = make_float4(NI, NI, NI, NI);

    const int pidx = blockIdx.x;  // plane index: n*512 + c
    const int tid  = threadIdx.x;
    const int n    = pidx >> 9;
    const int c    = pidx & 511;

    const float* gx   = x + (size_t)pidx * 4096;
    float*       gout = out + ((size_t)n * 2048 + (size_t)c) * 4096;

    // ---- Fill A (16B-aligned STS.128), copy x straight to out chunk 0, init pads ----
    {
        const float4* gx4 = (const float4*)gx;
        float4*       go4 = (float4*)gout;
#pragma unroll
        for (int i = 0; i < 4; i++) {
            int idx  = tid + i * 256;   // float4 index 0..1023
            float4 v = gx4[idx];
            go4[idx] = v;
            int row = idx >> 4;         // 16 float4 per row
            int c4  = idx & 15;
            *(float4*)&A[row * P + c4 * 4] = v;
        }
        if (tid < 64)  *(float4*)&A[tid * P + 64] = NI4;  // pad cols 64..67 per row
        if (tid == 64) *(float4*)&Araw[0]         = NI4;  // guard before row 0
    }
    __syncthreads();

    // h-pass mapping: row in warp (conflict-free .128 phases), 16-col segment
    const int hrow = tid & 63;
    const int hcs  = tid >> 6;          // col segment 0..3 (16 cols each)
    // v-pass mapping: 4-col group x 4-row group
    const int vc4 = tid & 15;           // float4 column 0..15
    const int vr0 = (tid >> 4) << 2;    // row base 0,4,...,60

#pragma unroll
    for (int level = 0; level < 3; level++) {
        // ---- horizontal max5: A -> B (6 LDS.128, 4 STS.128, no predication) ----
        {
            float w[24];
            const float* src = &A[hrow * P + hcs * 16 - 4];
#pragma unroll
            for (int k = 0; k < 6; k++) {
                float4 v = *(const float4*)(src + 4 * k);
                w[4 * k + 0] = v.x; w[4 * k + 1] = v.y;
                w[4 * k + 2] = v.z; w[4 * k + 3] = v.w;
            }
            float* dst = &B[hrow * P + hcs * 16];
#pragma unroll
            for (int m = 0; m < 4; m++) {
                float4 o;
                o.x = fmax5(w[4 * m + 2], w[4 * m + 3], w[4 * m + 4], w[4 * m + 5], w[4 * m + 6]);
                o.y = fmax5(w[4 * m + 3], w[4 * m + 4], w[4 * m + 5], w[4 * m + 6], w[4 * m + 7]);
                o.z = fmax5(w[4 * m + 4], w[4 * m + 5], w[4 * m + 6], w[4 * m + 7], w[4 * m + 8]);
                o.w = fmax5(w[4 * m + 5], w[4 * m + 6], w[4 * m + 7], w[4 * m + 8], w[4 * m + 9]);
                *(float4*)(dst + 4 * m) = o;
            }
        }
        __syncthreads();

        // ---- vertical max5: B -> A, + STG.128 of final result ----
        {
            float4 v[8];
#pragma unroll
            for (int k = 0; k < 8; k++) {
                int row = vr0 - 2 + k;
                v[k] = (row >= 0 && row < 64) ? *(const float4*)&B[row * P + vc4 * 4] : NI4;
            }
            float4* gl4 = (float4*)(gout + (size_t)(level + 1) * 512 * 4096);
#pragma unroll
            for (int j = 0; j < 4; j++) {
                float4 o = vmax5(v[j], v[j + 1], v[j + 2], v[j + 3], v[j + 4]);
                *(float4*)&A[(vr0 + j) * P + vc4 * 4] = o;
                gl4[(size_t)(vr0 + j) * 16 + vc4]     = o;
            }
        }
        __syncthreads();
    }
}

extern "C" void kernel_launch(void* const* d_in, const int* in_sizes, int n_in,
                              void* d_out, int out_size) {
    const float* x = (const float*)d_in[0];
    float* out = (float*)d_out;
    spp_kernel<<<8192, 256>>>(x, out);  // 16 * 512 planes
}